// round 11
// baseline (speedup 1.0000x reference)
#include <cuda_runtime.h>
#include <math.h>

#define BS 64
#define NUM_CAMS 6
#define NJ 20
#define NPIX 4096          // 64*64
#define NMAPS (BS*NUM_CAMS*NJ)   // 7680

// Output layout (tuple order, flattened):
//   kp_3d : (BS, NJ, 3)            -> 3840
//   res   : (BS, NJ)               -> 1280
//   kpc   : (BS, NUM_CAMS, NJ, 3)  -> 23040
//   kph   : (BS, NUM_CAMS, NJ, 3)  -> 23040
#define OFF_KP3D 0
#define OFF_RES  (BS*NJ*3)                     // 3840
#define OFF_KPC  (OFF_RES + BS*NJ)             // 5120
#define OFF_KPH  (OFF_KPC + BS*NUM_CAMS*NJ*3)  // 28160

// ---------------------------------------------------------------------------
// Kernel 1: per-(cam-batch, joint) soft-argmax over 64x64 heatmap.
// ---------------------------------------------------------------------------
__global__ __launch_bounds__(256)
void softargmax_kernel(const float* __restrict__ hm, float* __restrict__ out)
{
    const int map = blockIdx.x;                 // 0..7679
    const float* p = hm + (size_t)map * NPIX;
    const int t = threadIdx.x;

    float vals[16];
    float lmax = -1e30f;
#pragma unroll
    for (int i = 0; i < 4; i++) {
        float4 v = __ldcs(reinterpret_cast<const float4*>(p) + i * 256 + t);
        vals[i*4+0] = v.x * 100.0f;
        vals[i*4+1] = v.y * 100.0f;
        vals[i*4+2] = v.z * 100.0f;
        vals[i*4+3] = v.w * 100.0f;
        lmax = fmaxf(lmax, fmaxf(fmaxf(vals[i*4+0], vals[i*4+1]),
                                 fmaxf(vals[i*4+2], vals[i*4+3])));
    }

    __shared__ float smax[8];
    __shared__ float sacc[3][8];

    const int wid  = t >> 5;
    const int lane = t & 31;

#pragma unroll
    for (int o = 16; o > 0; o >>= 1)
        lmax = fmaxf(lmax, __shfl_xor_sync(0xffffffffu, lmax, o));
    if (lane == 0) smax[wid] = lmax;
    __syncthreads();
    float m;
    {
        float v0 = smax[0];
#pragma unroll
        for (int w = 1; w < 8; w++) v0 = fmaxf(v0, smax[w]);
        m = v0;
    }

    // exp + weighted sums. expf(x) == 0 exactly for x < ~-104, so skipping
    // those terms matches the reference bit-for-bit (mod summation order).
    float s = 0.f, sx = 0.f, sy = 0.f;
#pragma unroll
    for (int i = 0; i < 4; i++) {
#pragma unroll
        for (int u = 0; u < 4; u++) {
            float d = vals[i*4+u] - m;
            if (__ballot_sync(0xffffffffu, d > -104.0f)) {
                if (d > -104.0f) {
                    float e = expf(d);
                    int idx = i * 1024 + t * 4 + u;   // linear pixel index
                    s  += e;
                    sx += e * (float)(idx & 63);      // column (x)
                    sy += e * (float)(idx >> 6);      // row (y)
                }
            }
        }
    }

#pragma unroll
    for (int o = 16; o > 0; o >>= 1) {
        s  += __shfl_xor_sync(0xffffffffu, s,  o);
        sx += __shfl_xor_sync(0xffffffffu, sx, o);
        sy += __shfl_xor_sync(0xffffffffu, sy, o);
    }
    if (lane == 0) { sacc[0][wid] = s; sacc[1][wid] = sx; sacc[2][wid] = sy; }
    __syncthreads();

    if (t == 0) {
        float S = 0.f, X = 0.f, Y = 0.f;
#pragma unroll
        for (int w = 0; w < 8; w++) { S += sacc[0][w]; X += sacc[1][w]; Y += sacc[2][w]; }
        float recS = 1.0f / S;        // == max(softmax) (peak term is exp(0)=1)
        float x = X * recS;
        float y = Y * recS;
        float* kph = out + OFF_KPH + map * 3;
        float* kpc = out + OFF_KPC + map * 3;
        kph[0] = x;        kph[1] = y;        kph[2] = recS;
        kpc[0] = x * 4.0f; kpc[1] = y * 4.0f; kpc[2] = recS;   // 256/64 = 4
    }
}

// ---------------------------------------------------------------------------
// fp64 helpers (float-seeded Newton; operands guaranteed float-range by callers)
// ---------------------------------------------------------------------------
__device__ __forceinline__ double fast_drcp(double d)        // ~2^-48 rel
{
    double r = (double)__frcp_rn((float)d);
    r = r * (2.0 - d * r);
    return r;
}

__device__ __forceinline__ double fast_drsqrt(double d)      // ~2^-46 rel
{
    double r = (double)__frsqrt_rn((float)d);
    r = r * (1.5 - 0.5 * d * r * r);
    return r;
}

// exact power-of-two ~ 1/sqrt(d): zero rounding perturbation, full fp64 range.
__device__ __forceinline__ double pow2_inv_sqrt_approx(double d)
{
    int hi = __double2hiint(d);
    int e  = ((hi >> 20) & 0x7ff) - 1023;   // floor(log2 d)
    int k  = -(e >> 1);                     // ~ -e/2 (within 1)
    return __hiloint2double((1023 + k) << 20, 0);
}

// ---------------------------------------------------------------------------
// Paired Jacobi rotations in commuting (disjoint) planes, divide-free and
// cancellation-free:
//   rho = sqrt(u^2+w^2); c^2 = (|u|+rho)/(2 rho)   (additions only)
//   ic  = rsqrt(c^2) = 1/c; c = c^2*ic
//   s   = sign(u) * w * (1/(2 rho)) * ic           (== t*c identically)
//   t   = s * ic                                   (== s/c)
// Exact identity at degenerate z via selects (c=1, s=t=0).
// ---------------------------------------------------------------------------
template<int P, int Q, int R, int S>
__device__ __forceinline__ void jrot_pair(float M[4][4], float V[4][4])
{
    float apq = M[P][Q],            ars = M[R][S];
    float u1  = M[Q][Q] - M[P][P],  u2  = M[S][S] - M[R][R];
    float w1  = 2.0f * apq,         w2  = 2.0f * ars;
    float z1  = fmaf(u1, u1, w1*w1), z2 = fmaf(u2, u2, w2*w2);
    bool  g1  = (z1 > 1e-30f),      g2  = (z2 > 1e-30f);

    float ir1 = rsqrtf(z1),         ir2 = rsqrtf(z2);      // 1/rho
    float hr1 = 0.5f * ir1,         hr2 = 0.5f * ir2;      // 1/(2 rho)
    float rho1 = z1 * ir1,          rho2 = z2 * ir2;       // rho
    float c2a = (fabsf(u1) + rho1) * hr1;                  // c^2 in [0.5,1]
    float c2b = (fabsf(u2) + rho2) * hr2;
    float ica = rsqrtf(c2a),        icb = rsqrtf(c2b);     // 1/c
    float ca  = c2a * ica,          cb  = c2b * icb;       // c
    float sa  = ((u1 >= 0.0f) ? w1 : -w1) * hr1 * ica;     // s
    float sb  = ((u2 >= 0.0f) ? w2 : -w2) * hr2 * icb;
    float taa = sa * ica,           tbb = sb * icb;        // t = s/c

    float c1 = g1 ? ca  : 1.0f,  s1 = g1 ? sa : 0.0f,  t1 = g1 ? taa : 0.0f;
    float c2 = g2 ? cb  : 1.0f,  s2 = g2 ? sb : 0.0f,  t2 = g2 ? tbb : 0.0f;

    // in-plane diagonal updates (exact tau-form identities)
    M[P][P] = fmaf(-t1, apq, M[P][P]);
    M[Q][Q] = fmaf( t1, apq, M[Q][Q]);
    M[R][R] = fmaf(-t2, ars, M[R][R]);
    M[S][S] = fmaf( t2, ars, M[S][S]);
    M[P][Q] = 0.0f; M[Q][P] = 0.0f;
    M[R][S] = 0.0f; M[S][R] = 0.0f;

    // cross block: rows {P,Q} x cols {R,S}; R1 then R2 (commuting planes)
    float bpr = M[P][R], bps = M[P][S], bqr = M[Q][R], bqs = M[Q][S];
    float upr = c1 * bpr - s1 * bqr;
    float uqr = s1 * bpr + c1 * bqr;
    float ups = c1 * bps - s1 * bqs;
    float uqs = s1 * bps + c1 * bqs;
    float npr = c2 * upr - s2 * ups;
    float nps = s2 * upr + c2 * ups;
    float nqr = c2 * uqr - s2 * uqs;
    float nqs = s2 * uqr + c2 * uqs;
    M[P][R] = npr; M[R][P] = npr;  M[P][S] = nps; M[S][P] = nps;
    M[Q][R] = nqr; M[R][Q] = nqr;  M[Q][S] = nqs; M[S][Q] = nqs;

    // eigenvector columns
#pragma unroll
    for (int r = 0; r < 4; r++) {
        float vp = V[r][P], vq = V[r][Q];
        V[r][P] = c1 * vp - s1 * vq;
        V[r][Q] = s1 * vp + c1 * vq;
        float vr = V[r][R], vs = V[r][S];
        V[r][R] = c2 * vr - s2 * vs;
        V[r][S] = s2 * vr + c2 * vs;
    }
}

__global__ __launch_bounds__(32)
void triangulate_kernel(const float* __restrict__ proj,
                        const float* __restrict__ confid,
                        float* __restrict__ out)
{
    const int tidx = blockIdx.x * blockDim.x + threadIdx.x;
    if (tidx >= BS * NJ) return;
    const int b = tidx / NJ;
    const int j = tidx % NJ;

    // ---- issue ALL loads up front (independent; ~1 round trip total) -----
    const float* kpc = out + OFF_KPC;
    float conf6[NUM_CAMS], px[NUM_CAMS], py[NUM_CAMS];
    float4 r0[NUM_CAMS], r1[NUM_CAMS], r2[NUM_CAMS];
#pragma unroll
    for (int c = 0; c < NUM_CAMS; c++) {
        conf6[c] = confid[(b * NUM_CAMS + c) * NJ + j];
        px[c] = kpc[((b * NUM_CAMS + c) * NJ + j) * 3 + 0];
        py[c] = kpc[((b * NUM_CAMS + c) * NJ + j) * 3 + 1];
        const float4* Pc4 = reinterpret_cast<const float4*>(proj + (b * NUM_CAMS + c) * 12);
        r0[c] = Pc4[0]; r1[c] = Pc4[1]; r2[c] = Pc4[2];
    }

    // normalized per-camera confidences (single reciprocal)
    float csum = 0.f;
#pragma unroll
    for (int c = 0; c < NUM_CAMS; c++) csum += conf6[c];
    float rs = 1.0f / csum;
    float cf[NUM_CAMS];
#pragma unroll
    for (int c = 0; c < NUM_CAMS; c++) cf[c] = fmaf(conf6[c], rs, 1e-5f);

    // Build A (12x4) in fp32
    float Af[12][4];
#pragma unroll
    for (int c = 0; c < NUM_CAMS; c++) {
        float p0[4] = { r0[c].x, r0[c].y, r0[c].z, r0[c].w };
        float p1[4] = { r1[c].x, r1[c].y, r1[c].z, r1[c].w };
        float p2[4] = { r2[c].x, r2[c].y, r2[c].z, r2[c].w };
#pragma unroll
        for (int k = 0; k < 4; k++) {
            Af[c*2+0][k] = (p2[k] * px[c] - p0[k]) * cf[c];
            Af[c*2+1][k] = (p2[k] * py[c] - p1[k]) * cf[c];
        }
    }

    // ---------------- fp64 M = AtA, 3-way split accumulation (depth ~6) ---
    double M[4][4];
#pragma unroll
    for (int k = 0; k < 4; k++) {
#pragma unroll
        for (int l = k; l < 4; l++) {
            double g0 = 0.0, g1 = 0.0, g2 = 0.0;
#pragma unroll
            for (int n = 0; n < 4; n++) {
                g0 = fma((double)Af[n    ][k], (double)Af[n    ][l], g0);
                g1 = fma((double)Af[n + 4][k], (double)Af[n + 4][l], g1);
                g2 = fma((double)Af[n + 8][k], (double)Af[n + 8][l], g2);
            }
            double v = (g0 + g1) + g2;
            M[k][l] = v; M[l][k] = v;
        }
    }

    // ---------------- fp32 Jacobi (paired commuting rotations, 5 sweeps) --
    float M32[4][4], V32[4][4];
#pragma unroll
    for (int k = 0; k < 4; k++)
#pragma unroll
        for (int l = 0; l < 4; l++) {
            M32[k][l] = (float)M[k][l];
            V32[k][l] = (k == l) ? 1.0f : 0.0f;
        }

#pragma unroll
    for (int sweep = 0; sweep < 5; sweep++) {
        jrot_pair<0,1,2,3>(M32, V32);
        jrot_pair<0,2,1,3>(M32, V32);
        jrot_pair<0,3,1,2>(M32, V32);
    }

    // seed selection: fp32 diagonal argmin
    int mi = 0; float dmf = M32[0][0];
    if (M32[1][1] < dmf) { dmf = M32[1][1]; mi = 1; }
    if (M32[2][2] < dmf) { dmf = M32[2][2]; mi = 2; }
    if (M32[3][3] < dmf) { dmf = M32[3][3]; mi = 3; }

    double x0 = (double)((mi == 0) ? V32[0][0] : (mi == 1) ? V32[0][1] : (mi == 2) ? V32[0][2] : V32[0][3]);
    double x1 = (double)((mi == 0) ? V32[1][0] : (mi == 1) ? V32[1][1] : (mi == 2) ? V32[1][2] : V32[1][3]);
    double x2 = (double)((mi == 0) ? V32[2][0] : (mi == 1) ? V32[2][1] : (mi == 2) ? V32[2][2] : V32[2][3]);
    double x3 = (double)((mi == 0) ? V32[3][0] : (mi == 1) ? V32[3][1] : (mi == 2) ? V32[3][2] : V32[3][3]);

    // ---------------- adjugate of symmetric 4x4 M (2x2-subdet form) -------
    double s0 = fma(M[0][0], M[1][1], -M[1][0] * M[0][1]);
    double s1 = fma(M[0][0], M[1][2], -M[1][0] * M[0][2]);
    double s2 = fma(M[0][0], M[1][3], -M[1][0] * M[0][3]);
    double s3 = fma(M[0][1], M[1][2], -M[1][1] * M[0][2]);
    double s4 = fma(M[0][1], M[1][3], -M[1][1] * M[0][3]);
    double s5 = fma(M[0][2], M[1][3], -M[1][2] * M[0][3]);
    double c5 = fma(M[2][2], M[3][3], -M[3][2] * M[2][3]);
    double c4 = fma(M[2][1], M[3][3], -M[3][1] * M[2][3]);
    double c3 = fma(M[2][1], M[3][2], -M[3][1] * M[2][2]);
    double c2 = fma(M[2][0], M[3][3], -M[3][0] * M[2][3]);
    double c1 = fma(M[2][0], M[3][2], -M[3][0] * M[2][2]);

    double J00 = fma( M[1][1], c5, fma(-M[1][2], c4,  M[1][3] * c3));
    double J01 = fma(-M[0][1], c5, fma( M[0][2], c4, -M[0][3] * c3));
    double J02 = fma( M[3][1], s5, fma(-M[3][2], s4,  M[3][3] * s3));
    double J03 = fma(-M[2][1], s5, fma( M[2][2], s4, -M[2][3] * s3));
    double J11 = fma( M[0][0], c5, fma(-M[0][2], c2,  M[0][3] * c1));
    double J12 = fma(-M[3][0], s5, fma( M[3][2], s2, -M[3][3] * s1));
    double J13 = fma( M[2][0], s5, fma(-M[2][2], s2,  M[2][3] * s1));
    double J22 = fma( M[3][0], s4, fma(-M[3][1], s2,  M[3][3] * s0));
    double J23 = fma(-M[2][0], s4, fma( M[2][1], s2, -M[2][3] * s0));
    double J33 = fma( M[2][0], s3, fma(-M[2][1], s1,  M[2][2] * s0));

    // two adjugate applications, NO mid renorm (||x||^2 stays << fp64 max)
    double y0 = fma(J00, x0, fma(J01, x1, fma(J02, x2, J03 * x3)));
    double y1 = fma(J01, x0, fma(J11, x1, fma(J12, x2, J13 * x3)));
    double y2 = fma(J02, x0, fma(J12, x1, fma(J22, x2, J23 * x3)));
    double y3 = fma(J03, x0, fma(J13, x1, fma(J23, x2, J33 * x3)));
    x0 = fma(J00, y0, fma(J01, y1, fma(J02, y2, J03 * y3)));
    x1 = fma(J01, y0, fma(J11, y1, fma(J12, y2, J13 * y3)));
    x2 = fma(J02, y0, fma(J12, y1, fma(J22, y2, J23 * y3)));
    x3 = fma(J03, y0, fma(J13, y1, fma(J23, y2, J33 * y3)));

    // exact pow2 renorm; nrm2 of the scaled vector is (n2*sc)*sc EXACTLY
    double n2 = fma(x0, x0, fma(x1, x1, fma(x2, x2, x3 * x3)));
    double sc = pow2_inv_sqrt_approx(n2);
    x0 *= sc; x1 *= sc; x2 *= sc; x3 *= sc;
    double nrm2 = (n2 * sc) * sc;               // in ~[0.25, 4]

    // kp_3d = x[:3]/x[3]  (normalization- and sign-invariant)
    double inv = fast_drcp(x3);
    float* kp3 = out + OFF_KP3D + tidx * 3;
    kp3[0] = (float)(x0 * inv);
    kp3[1] = (float)(x1 * inv);
    kp3[2] = (float)(x2 * inv);

    // res = (sum_n |A[n,:].x|) / ||x||   -- 3 parallel chains of 4
    double a0 = 0.0, a1 = 0.0, a2 = 0.0;
#pragma unroll
    for (int n = 0; n < 4; n++) {
        a0 += fabs(fma((double)Af[n    ][0], x0, fma((double)Af[n    ][1], x1,
                   fma((double)Af[n    ][2], x2, (double)Af[n    ][3] * x3))));
        a1 += fabs(fma((double)Af[n + 4][0], x0, fma((double)Af[n + 4][1], x1,
                   fma((double)Af[n + 4][2], x2, (double)Af[n + 4][3] * x3))));
        a2 += fabs(fma((double)Af[n + 8][0], x0, fma((double)Af[n + 8][1], x1,
                   fma((double)Af[n + 8][2], x2, (double)Af[n + 8][3] * x3))));
    }
    double acc = (a0 + a1) + a2;
    out[OFF_RES + tidx] = (float)(acc * fast_drsqrt(nrm2));
}

// ---------------------------------------------------------------------------
extern "C" void kernel_launch(void* const* d_in, const int* in_sizes, int n_in,
                              void* d_out, int out_size)
{
    const float* heatmap = (const float*)d_in[0];  // (384, 20, 64, 64)
    const float* proj    = (const float*)d_in[1];  // (64, 6, 3, 4)
    const float* confid  = (const float*)d_in[2];  // (384, 20)
    float* out = (float*)d_out;                    // 51200 floats

    softargmax_kernel<<<NMAPS, 256>>>(heatmap, out);
    triangulate_kernel<<<(BS * NJ + 31) / 32, 32>>>(proj, confid, out);
}

// round 12
// speedup vs baseline: 1.1241x; 1.1241x over previous
#include <cuda_runtime.h>
#include <math.h>

#define BS 64
#define NUM_CAMS 6
#define NJ 20
#define NPIX 4096          // 64*64
#define NMAPS (BS*NUM_CAMS*NJ)   // 7680

// Output layout (tuple order, flattened):
//   kp_3d : (BS, NJ, 3)            -> 3840
//   res   : (BS, NJ)               -> 1280
//   kpc   : (BS, NUM_CAMS, NJ, 3)  -> 23040
//   kph   : (BS, NUM_CAMS, NJ, 3)  -> 23040
#define OFF_KP3D 0
#define OFF_RES  (BS*NJ*3)                     // 3840
#define OFF_KPC  (OFF_RES + BS*NJ)             // 5120
#define OFF_KPH  (OFF_KPC + BS*NUM_CAMS*NJ*3)  // 28160

// ---------------------------------------------------------------------------
// Kernel 1: per-(cam-batch, joint) soft-argmax over 64x64 heatmap.
// (unchanged -- near HBM roof)
// ---------------------------------------------------------------------------
__global__ __launch_bounds__(256)
void softargmax_kernel(const float* __restrict__ hm, float* __restrict__ out)
{
    const int map = blockIdx.x;                 // 0..7679
    const float* p = hm + (size_t)map * NPIX;
    const int t = threadIdx.x;

    float vals[16];
    float lmax = -1e30f;
#pragma unroll
    for (int i = 0; i < 4; i++) {
        float4 v = __ldcs(reinterpret_cast<const float4*>(p) + i * 256 + t);
        vals[i*4+0] = v.x * 100.0f;
        vals[i*4+1] = v.y * 100.0f;
        vals[i*4+2] = v.z * 100.0f;
        vals[i*4+3] = v.w * 100.0f;
        lmax = fmaxf(lmax, fmaxf(fmaxf(vals[i*4+0], vals[i*4+1]),
                                 fmaxf(vals[i*4+2], vals[i*4+3])));
    }

    __shared__ float smax[8];
    __shared__ float sacc[3][8];

    const int wid  = t >> 5;
    const int lane = t & 31;

#pragma unroll
    for (int o = 16; o > 0; o >>= 1)
        lmax = fmaxf(lmax, __shfl_xor_sync(0xffffffffu, lmax, o));
    if (lane == 0) smax[wid] = lmax;
    __syncthreads();
    float m;
    {
        float v0 = smax[0];
#pragma unroll
        for (int w = 1; w < 8; w++) v0 = fmaxf(v0, smax[w]);
        m = v0;
    }

    // exp + weighted sums. expf(x) == 0 exactly for x < ~-104, so skipping
    // those terms matches the reference bit-for-bit (mod summation order).
    float s = 0.f, sx = 0.f, sy = 0.f;
#pragma unroll
    for (int i = 0; i < 4; i++) {
#pragma unroll
        for (int u = 0; u < 4; u++) {
            float d = vals[i*4+u] - m;
            if (__ballot_sync(0xffffffffu, d > -104.0f)) {
                if (d > -104.0f) {
                    float e = expf(d);
                    int idx = i * 1024 + t * 4 + u;   // linear pixel index
                    s  += e;
                    sx += e * (float)(idx & 63);      // column (x)
                    sy += e * (float)(idx >> 6);      // row (y)
                }
            }
        }
    }

#pragma unroll
    for (int o = 16; o > 0; o >>= 1) {
        s  += __shfl_xor_sync(0xffffffffu, s,  o);
        sx += __shfl_xor_sync(0xffffffffu, sx, o);
        sy += __shfl_xor_sync(0xffffffffu, sy, o);
    }
    if (lane == 0) { sacc[0][wid] = s; sacc[1][wid] = sx; sacc[2][wid] = sy; }
    __syncthreads();

    if (t == 0) {
        float S = 0.f, X = 0.f, Y = 0.f;
#pragma unroll
        for (int w = 0; w < 8; w++) { S += sacc[0][w]; X += sacc[1][w]; Y += sacc[2][w]; }
        float recS = 1.0f / S;        // == max(softmax) (peak term is exp(0)=1)
        float x = X * recS;
        float y = Y * recS;
        float* kph = out + OFF_KPH + map * 3;
        float* kpc = out + OFF_KPC + map * 3;
        kph[0] = x;        kph[1] = y;        kph[2] = recS;
        kpc[0] = x * 4.0f; kpc[1] = y * 4.0f; kpc[2] = recS;   // 256/64 = 4
    }
}

// ---------------------------------------------------------------------------
// fp64 helpers (float-seeded Newton; operands guaranteed float-range by callers)
// ---------------------------------------------------------------------------
__device__ __forceinline__ double fast_drcp(double d)        // ~2^-48 rel
{
    double r = (double)__frcp_rn((float)d);
    r = r * (2.0 - d * r);
    return r;
}

__device__ __forceinline__ double fast_drsqrt(double d)      // ~2^-46 rel
{
    double r = (double)__frsqrt_rn((float)d);
    r = r * (1.5 - 0.5 * d * r * r);
    return r;
}

// exact power-of-two ~ 1/sqrt(d): zero rounding perturbation, full fp64 range.
__device__ __forceinline__ double pow2_inv_sqrt_approx(double d)
{
    int hi = __double2hiint(d);
    int e  = ((hi >> 20) & 0x7ff) - 1023;   // floor(log2 d)
    int k  = -(e >> 1);                     // ~ -e/2 (within 1)
    return __hiloint2double((1023 + k) << 20, 0);
}

// ---------------------------------------------------------------------------
// Paired Jacobi rotations in commuting (disjoint) planes (R11, proven).
// ---------------------------------------------------------------------------
template<int P, int Q, int R, int S>
__device__ __forceinline__ void jrot_pair(float M[4][4], float V[4][4])
{
    float apq = M[P][Q],            ars = M[R][S];
    float u1  = M[Q][Q] - M[P][P],  u2  = M[S][S] - M[R][R];
    float w1  = 2.0f * apq,         w2  = 2.0f * ars;
    float z1  = fmaf(u1, u1, w1*w1), z2 = fmaf(u2, u2, w2*w2);
    bool  g1  = (z1 > 1e-30f),      g2  = (z2 > 1e-30f);

    float ir1 = rsqrtf(z1),         ir2 = rsqrtf(z2);      // 1/rho
    float hr1 = 0.5f * ir1,         hr2 = 0.5f * ir2;      // 1/(2 rho)
    float rho1 = z1 * ir1,          rho2 = z2 * ir2;       // rho
    float c2a = (fabsf(u1) + rho1) * hr1;                  // c^2 in [0.5,1]
    float c2b = (fabsf(u2) + rho2) * hr2;
    float ica = rsqrtf(c2a),        icb = rsqrtf(c2b);     // 1/c
    float ca  = c2a * ica,          cb  = c2b * icb;       // c
    float sa  = ((u1 >= 0.0f) ? w1 : -w1) * hr1 * ica;     // s
    float sb  = ((u2 >= 0.0f) ? w2 : -w2) * hr2 * icb;
    float taa = sa * ica,           tbb = sb * icb;        // t = s/c

    float c1 = g1 ? ca  : 1.0f,  s1 = g1 ? sa : 0.0f,  t1 = g1 ? taa : 0.0f;
    float c2 = g2 ? cb  : 1.0f,  s2 = g2 ? sb : 0.0f,  t2 = g2 ? tbb : 0.0f;

    M[P][P] = fmaf(-t1, apq, M[P][P]);
    M[Q][Q] = fmaf( t1, apq, M[Q][Q]);
    M[R][R] = fmaf(-t2, ars, M[R][R]);
    M[S][S] = fmaf( t2, ars, M[S][S]);
    M[P][Q] = 0.0f; M[Q][P] = 0.0f;
    M[R][S] = 0.0f; M[S][R] = 0.0f;

    float bpr = M[P][R], bps = M[P][S], bqr = M[Q][R], bqs = M[Q][S];
    float upr = c1 * bpr - s1 * bqr;
    float uqr = s1 * bpr + c1 * bqr;
    float ups = c1 * bps - s1 * bqs;
    float uqs = s1 * bps + c1 * bqs;
    float npr = c2 * upr - s2 * ups;
    float nps = s2 * upr + c2 * ups;
    float nqr = c2 * uqr - s2 * uqs;
    float nqs = s2 * uqr + c2 * uqs;
    M[P][R] = npr; M[R][P] = npr;  M[P][S] = nps; M[S][P] = nps;
    M[Q][R] = nqr; M[R][Q] = nqr;  M[Q][S] = nqs; M[S][Q] = nqs;

#pragma unroll
    for (int r = 0; r < 4; r++) {
        float vp = V[r][P], vq = V[r][Q];
        V[r][P] = c1 * vp - s1 * vq;
        V[r][Q] = s1 * vp + c1 * vq;
        float vr = V[r][R], vs = V[r][S];
        V[r][R] = c2 * vr - s2 * vs;
        V[r][S] = s2 * vr + c2 * vs;
    }
}

// ---------------------------------------------------------------------------
// Kernel 2: DLT triangulation, 4 LANES PER JOINT (8 joints per warp).
// Row-parallel parts (A-build, fp64 AtA, res) are distributed across the
// quad's lanes (divides the fp64 SIMT stream ~4x -- it is issue-throughput
// bound at ~18 cyc/warp-DFMA); Jacobi/adjugate/applies stay replicated
// (identical numerics to R11). Quad butterfly shuffles combine partials.
// ---------------------------------------------------------------------------
__global__ __launch_bounds__(32)
void triangulate_kernel(const float* __restrict__ proj,
                        const float* __restrict__ confid,
                        float* __restrict__ out)
{
    const int lane  = threadIdx.x;          // 0..31
    const int quad  = lane >> 2;            // 0..7 : joint within warp
    const int ql    = lane & 3;             // 0..3 : row-group within joint
    const int joint = blockIdx.x * 8 + quad; // 0..1279 (grid=160 exact)
    const int b = joint / NJ;
    const int j = joint % NJ;

    // ---- confidence normalization (replicated; 6 scalar loads, broadcast) --
    float csum = 0.f;
#pragma unroll
    for (int c = 0; c < NUM_CAMS; c++)
        csum += confid[(b * NUM_CAMS + c) * NJ + j];
    const float rs = 1.0f / csum;

    // ---- this lane's 3 rows of A (rows 3*ql .. 3*ql+2) ---------------------
    // row n: cam = n>>1, parity = n&1:  A_n = (P_row2 * (par? py:px) - P_row{par}) * cf
    const float* kpc = out + OFF_KPC;
    float Af[3][4];
#pragma unroll
    for (int i = 0; i < 3; i++) {
        int n   = 3 * ql + i;
        int cam = n >> 1;
        int par = n & 1;
        const float* Pc = proj + (b * NUM_CAMS + cam) * 12;
        float4 prow = *reinterpret_cast<const float4*>(Pc + par * 4);   // row 0 or 1
        float4 p2   = *reinterpret_cast<const float4*>(Pc + 8);         // row 2
        float  cf   = fmaf(confid[(b * NUM_CAMS + cam) * NJ + j], rs, 1e-5f);
        float  uv   = kpc[((b * NUM_CAMS + cam) * NJ + j) * 3 + par];   // px or py
        Af[i][0] = (p2.x * uv - prow.x) * cf;
        Af[i][1] = (p2.y * uv - prow.y) * cf;
        Af[i][2] = (p2.z * uv - prow.z) * cf;
        Af[i][3] = (p2.w * uv - prow.w) * cf;
    }

    // ---- fp64 M = AtA: per-lane partials over 3 rows, quad butterfly sum ---
    const int PK[10] = {0,0,0,0,1,1,1,2,2,3};
    const int PL[10] = {0,1,2,3,1,2,3,2,3,3};
    double Ad[3][4];
#pragma unroll
    for (int i = 0; i < 3; i++)
#pragma unroll
        for (int k = 0; k < 4; k++) Ad[i][k] = (double)Af[i][k];

    double M[4][4];
#pragma unroll
    for (int e = 0; e < 10; e++) {
        double v = Ad[0][PK[e]] * Ad[0][PL[e]];
        v = fma(Ad[1][PK[e]], Ad[1][PL[e]], v);
        v = fma(Ad[2][PK[e]], Ad[2][PL[e]], v);
        v += __shfl_xor_sync(0xffffffffu, v, 1);
        v += __shfl_xor_sync(0xffffffffu, v, 2);
        M[PK[e]][PL[e]] = v;
        M[PL[e]][PK[e]] = v;
    }

    // ---- fp32 Jacobi (replicated across quad; identical to R11) -----------
    float M32[4][4], V32[4][4];
#pragma unroll
    for (int k = 0; k < 4; k++)
#pragma unroll
        for (int l = 0; l < 4; l++) {
            M32[k][l] = (float)M[k][l];
            V32[k][l] = (k == l) ? 1.0f : 0.0f;
        }

#pragma unroll
    for (int sweep = 0; sweep < 5; sweep++) {
        jrot_pair<0,1,2,3>(M32, V32);
        jrot_pair<0,2,1,3>(M32, V32);
        jrot_pair<0,3,1,2>(M32, V32);
    }

    int mi = 0; float dmf = M32[0][0];
    if (M32[1][1] < dmf) { dmf = M32[1][1]; mi = 1; }
    if (M32[2][2] < dmf) { dmf = M32[2][2]; mi = 2; }
    if (M32[3][3] < dmf) { dmf = M32[3][3]; mi = 3; }

    double x0 = (double)((mi == 0) ? V32[0][0] : (mi == 1) ? V32[0][1] : (mi == 2) ? V32[0][2] : V32[0][3]);
    double x1 = (double)((mi == 0) ? V32[1][0] : (mi == 1) ? V32[1][1] : (mi == 2) ? V32[1][2] : V32[1][3]);
    double x2 = (double)((mi == 0) ? V32[2][0] : (mi == 1) ? V32[2][1] : (mi == 2) ? V32[2][2] : V32[2][3]);
    double x3 = (double)((mi == 0) ? V32[3][0] : (mi == 1) ? V32[3][1] : (mi == 2) ? V32[3][2] : V32[3][3]);

    // ---- adjugate of symmetric M (replicated; identical to R11) -----------
    double s0 = fma(M[0][0], M[1][1], -M[1][0] * M[0][1]);
    double s1 = fma(M[0][0], M[1][2], -M[1][0] * M[0][2]);
    double s2 = fma(M[0][0], M[1][3], -M[1][0] * M[0][3]);
    double s3 = fma(M[0][1], M[1][2], -M[1][1] * M[0][2]);
    double s4 = fma(M[0][1], M[1][3], -M[1][1] * M[0][3]);
    double s5 = fma(M[0][2], M[1][3], -M[1][2] * M[0][3]);
    double c5 = fma(M[2][2], M[3][3], -M[3][2] * M[2][3]);
    double c4 = fma(M[2][1], M[3][3], -M[3][1] * M[2][3]);
    double c3 = fma(M[2][1], M[3][2], -M[3][1] * M[2][2]);
    double c2 = fma(M[2][0], M[3][3], -M[3][0] * M[2][3]);
    double c1 = fma(M[2][0], M[3][2], -M[3][0] * M[2][2]);

    double J00 = fma( M[1][1], c5, fma(-M[1][2], c4,  M[1][3] * c3));
    double J01 = fma(-M[0][1], c5, fma( M[0][2], c4, -M[0][3] * c3));
    double J02 = fma( M[3][1], s5, fma(-M[3][2], s4,  M[3][3] * s3));
    double J03 = fma(-M[2][1], s5, fma( M[2][2], s4, -M[2][3] * s3));
    double J11 = fma( M[0][0], c5, fma(-M[0][2], c2,  M[0][3] * c1));
    double J12 = fma(-M[3][0], s5, fma( M[3][2], s2, -M[3][3] * s1));
    double J13 = fma( M[2][0], s5, fma(-M[2][2], s2,  M[2][3] * s1));
    double J22 = fma( M[3][0], s4, fma(-M[3][1], s2,  M[3][3] * s0));
    double J23 = fma(-M[2][0], s4, fma( M[2][1], s2, -M[2][3] * s0));
    double J33 = fma( M[2][0], s3, fma(-M[2][1], s1,  M[2][2] * s0));

    // two adjugate applications, no mid renorm (||x||^2 << fp64 max)
    double y0 = fma(J00, x0, fma(J01, x1, fma(J02, x2, J03 * x3)));
    double y1 = fma(J01, x0, fma(J11, x1, fma(J12, x2, J13 * x3)));
    double y2 = fma(J02, x0, fma(J12, x1, fma(J22, x2, J23 * x3)));
    double y3 = fma(J03, x0, fma(J13, x1, fma(J23, x2, J33 * x3)));
    x0 = fma(J00, y0, fma(J01, y1, fma(J02, y2, J03 * y3)));
    x1 = fma(J01, y0, fma(J11, y1, fma(J12, y2, J13 * y3)));
    x2 = fma(J02, y0, fma(J12, y1, fma(J22, y2, J23 * y3)));
    x3 = fma(J03, y0, fma(J13, y1, fma(J23, y2, J33 * y3)));

    // exact pow2 renorm; nrm2 of scaled vector is (n2*sc)*sc EXACTLY
    double n2 = fma(x0, x0, fma(x1, x1, fma(x2, x2, x3 * x3)));
    double sc = pow2_inv_sqrt_approx(n2);
    x0 *= sc; x1 *= sc; x2 *= sc; x3 *= sc;
    double nrm2 = (n2 * sc) * sc;               // in ~[0.25, 4]

    // kp_3d = x[:3]/x[3]  (normalization- and sign-invariant); lane 0 of quad
    if (ql == 0) {
        double inv = fast_drcp(x3);
        float* kp3 = out + OFF_KP3D + joint * 3;
        kp3[0] = (float)(x0 * inv);
        kp3[1] = (float)(x1 * inv);
        kp3[2] = (float)(x2 * inv);
    }

    // res = (sum_n |A[n,:].x|) / ||x|| -- rows distributed, quad-reduced
    double acc = 0.0;
#pragma unroll
    for (int i = 0; i < 3; i++) {
        double dsum = fma(Ad[i][0], x0, fma(Ad[i][1], x1,
                      fma(Ad[i][2], x2, Ad[i][3] * x3)));
        acc += fabs(dsum);
    }
    acc += __shfl_xor_sync(0xffffffffu, acc, 1);
    acc += __shfl_xor_sync(0xffffffffu, acc, 2);
    if (ql == 0)
        out[OFF_RES + joint] = (float)(acc * fast_drsqrt(nrm2));
}

// ---------------------------------------------------------------------------
extern "C" void kernel_launch(void* const* d_in, const int* in_sizes, int n_in,
                              void* d_out, int out_size)
{
    const float* heatmap = (const float*)d_in[0];  // (384, 20, 64, 64)
    const float* proj    = (const float*)d_in[1];  // (64, 6, 3, 4)
    const float* confid  = (const float*)d_in[2];  // (384, 20)
    float* out = (float*)d_out;                    // 51200 floats

    softargmax_kernel<<<NMAPS, 256>>>(heatmap, out);
    triangulate_kernel<<<160, 32>>>(proj, confid, out);   // 160*8 = 1280 joints
}

// round 13
// speedup vs baseline: 1.1812x; 1.0507x over previous
#include <cuda_runtime.h>
#include <math.h>

#define BS 64
#define NUM_CAMS 6
#define NJ 20
#define NPIX 4096          // 64*64
#define NMAPS (BS*NUM_CAMS*NJ)   // 7680

// Output layout (tuple order, flattened):
//   kp_3d : (BS, NJ, 3)            -> 3840
//   res   : (BS, NJ)               -> 1280
//   kpc   : (BS, NUM_CAMS, NJ, 3)  -> 23040
//   kph   : (BS, NUM_CAMS, NJ, 3)  -> 23040
#define OFF_KP3D 0
#define OFF_RES  (BS*NJ*3)                     // 3840
#define OFF_KPC  (OFF_RES + BS*NJ)             // 5120
#define OFF_KPH  (OFF_KPC + BS*NUM_CAMS*NJ*3)  // 28160

// ---------------------------------------------------------------------------
// Kernel 1: per-(cam-batch, joint) soft-argmax over 64x64 heatmap.
// (unchanged -- near HBM roof)
// ---------------------------------------------------------------------------
__global__ __launch_bounds__(256)
void softargmax_kernel(const float* __restrict__ hm, float* __restrict__ out)
{
    const int map = blockIdx.x;                 // 0..7679
    const float* p = hm + (size_t)map * NPIX;
    const int t = threadIdx.x;

    float vals[16];
    float lmax = -1e30f;
#pragma unroll
    for (int i = 0; i < 4; i++) {
        float4 v = __ldcs(reinterpret_cast<const float4*>(p) + i * 256 + t);
        vals[i*4+0] = v.x * 100.0f;
        vals[i*4+1] = v.y * 100.0f;
        vals[i*4+2] = v.z * 100.0f;
        vals[i*4+3] = v.w * 100.0f;
        lmax = fmaxf(lmax, fmaxf(fmaxf(vals[i*4+0], vals[i*4+1]),
                                 fmaxf(vals[i*4+2], vals[i*4+3])));
    }

    __shared__ float smax[8];
    __shared__ float sacc[3][8];

    const int wid  = t >> 5;
    const int lane = t & 31;

#pragma unroll
    for (int o = 16; o > 0; o >>= 1)
        lmax = fmaxf(lmax, __shfl_xor_sync(0xffffffffu, lmax, o));
    if (lane == 0) smax[wid] = lmax;
    __syncthreads();
    float m;
    {
        float v0 = smax[0];
#pragma unroll
        for (int w = 1; w < 8; w++) v0 = fmaxf(v0, smax[w]);
        m = v0;
    }

    // exp + weighted sums. expf(x) == 0 exactly for x < ~-104, so skipping
    // those terms matches the reference bit-for-bit (mod summation order).
    float s = 0.f, sx = 0.f, sy = 0.f;
#pragma unroll
    for (int i = 0; i < 4; i++) {
#pragma unroll
        for (int u = 0; u < 4; u++) {
            float d = vals[i*4+u] - m;
            if (__ballot_sync(0xffffffffu, d > -104.0f)) {
                if (d > -104.0f) {
                    float e = expf(d);
                    int idx = i * 1024 + t * 4 + u;   // linear pixel index
                    s  += e;
                    sx += e * (float)(idx & 63);      // column (x)
                    sy += e * (float)(idx >> 6);      // row (y)
                }
            }
        }
    }

#pragma unroll
    for (int o = 16; o > 0; o >>= 1) {
        s  += __shfl_xor_sync(0xffffffffu, s,  o);
        sx += __shfl_xor_sync(0xffffffffu, sx, o);
        sy += __shfl_xor_sync(0xffffffffu, sy, o);
    }
    if (lane == 0) { sacc[0][wid] = s; sacc[1][wid] = sx; sacc[2][wid] = sy; }
    __syncthreads();

    if (t == 0) {
        float S = 0.f, X = 0.f, Y = 0.f;
#pragma unroll
        for (int w = 0; w < 8; w++) { S += sacc[0][w]; X += sacc[1][w]; Y += sacc[2][w]; }
        float recS = 1.0f / S;        // == max(softmax) (peak term is exp(0)=1)
        float x = X * recS;
        float y = Y * recS;
        float* kph = out + OFF_KPH + map * 3;
        float* kpc = out + OFF_KPC + map * 3;
        kph[0] = x;        kph[1] = y;        kph[2] = recS;
        kpc[0] = x * 4.0f; kpc[1] = y * 4.0f; kpc[2] = recS;   // 256/64 = 4
    }
}

// ---------------------------------------------------------------------------
// fp64 helpers (float-seeded Newton; operands guaranteed float-range by callers)
// ---------------------------------------------------------------------------
__device__ __forceinline__ double fast_drcp(double d)        // ~2^-48 rel
{
    double r = (double)__frcp_rn((float)d);
    r = r * (2.0 - d * r);
    return r;
}

__device__ __forceinline__ double fast_drsqrt(double d)      // ~2^-46 rel
{
    double r = (double)__frsqrt_rn((float)d);
    r = r * (1.5 - 0.5 * d * r * r);
    return r;
}

// exact power-of-two ~ 1/sqrt(d): zero rounding perturbation, full fp64 range.
__device__ __forceinline__ double pow2_inv_sqrt_approx(double d)
{
    int hi = __double2hiint(d);
    int e  = ((hi >> 20) & 0x7ff) - 1023;   // floor(log2 d)
    int k  = -(e >> 1);                     // ~ -e/2 (within 1)
    return __hiloint2double((1023 + k) << 20, 0);
}

// ---------------------------------------------------------------------------
// Paired Jacobi rotations in commuting (disjoint) planes (R11/R12 proven).
// V is LANE-DISTRIBUTED: each lane owns one eigenvector ROW (rows evolve
// independently under right-multiplication by rotations), so Vrow[4] is this
// lane's row only. Arithmetic per row is bit-identical to the replicated form.
// ---------------------------------------------------------------------------
template<int P, int Q, int R, int S>
__device__ __forceinline__ void jrot_pair(float M[4][4], float Vrow[4])
{
    float apq = M[P][Q],            ars = M[R][S];
    float u1  = M[Q][Q] - M[P][P],  u2  = M[S][S] - M[R][R];
    float w1  = 2.0f * apq,         w2  = 2.0f * ars;
    float z1  = fmaf(u1, u1, w1*w1), z2 = fmaf(u2, u2, w2*w2);
    bool  g1  = (z1 > 1e-30f),      g2  = (z2 > 1e-30f);

    float ir1 = rsqrtf(z1),         ir2 = rsqrtf(z2);      // 1/rho
    float hr1 = 0.5f * ir1,         hr2 = 0.5f * ir2;      // 1/(2 rho)
    float rho1 = z1 * ir1,          rho2 = z2 * ir2;       // rho
    float c2a = (fabsf(u1) + rho1) * hr1;                  // c^2 in [0.5,1]
    float c2b = (fabsf(u2) + rho2) * hr2;
    float ica = rsqrtf(c2a),        icb = rsqrtf(c2b);     // 1/c
    float ca  = c2a * ica,          cb  = c2b * icb;       // c
    float sa  = ((u1 >= 0.0f) ? w1 : -w1) * hr1 * ica;     // s
    float sb  = ((u2 >= 0.0f) ? w2 : -w2) * hr2 * icb;
    float taa = sa * ica,           tbb = sb * icb;        // t = s/c

    float c1 = g1 ? ca  : 1.0f,  s1 = g1 ? sa : 0.0f,  t1 = g1 ? taa : 0.0f;
    float c2 = g2 ? cb  : 1.0f,  s2 = g2 ? sb : 0.0f,  t2 = g2 ? tbb : 0.0f;

    M[P][P] = fmaf(-t1, apq, M[P][P]);
    M[Q][Q] = fmaf( t1, apq, M[Q][Q]);
    M[R][R] = fmaf(-t2, ars, M[R][R]);
    M[S][S] = fmaf( t2, ars, M[S][S]);
    M[P][Q] = 0.0f; M[Q][P] = 0.0f;
    M[R][S] = 0.0f; M[S][R] = 0.0f;

    float bpr = M[P][R], bps = M[P][S], bqr = M[Q][R], bqs = M[Q][S];
    float upr = c1 * bpr - s1 * bqr;
    float uqr = s1 * bpr + c1 * bqr;
    float ups = c1 * bps - s1 * bqs;
    float uqs = s1 * bps + c1 * bqs;
    float npr = c2 * upr - s2 * ups;
    float nps = s2 * upr + c2 * ups;
    float nqr = c2 * uqr - s2 * uqs;
    float nqs = s2 * uqr + c2 * uqs;
    M[P][R] = npr; M[R][P] = npr;  M[P][S] = nps; M[S][P] = nps;
    M[Q][R] = nqr; M[R][Q] = nqr;  M[Q][S] = nqs; M[S][Q] = nqs;

    // this lane's eigenvector row only (was replicated over 4 rows)
    float vp = Vrow[P], vq = Vrow[Q];
    Vrow[P] = c1 * vp - s1 * vq;
    Vrow[Q] = s1 * vp + c1 * vq;
    float vr = Vrow[R], vs = Vrow[S];
    Vrow[R] = c2 * vr - s2 * vs;
    Vrow[S] = s2 * vr + c2 * vs;
}

// ---------------------------------------------------------------------------
// Kernel 2: DLT triangulation, 4 LANES PER JOINT (8 joints per warp).
// Distributed across the quad: A-rows / fp64 AtA / res (R12), PLUS eigenvector
// rows in Jacobi and the adjugate mat-vec rows (this round). Jacobi-M,
// sub-determinants and J entries stay replicated (not SIMT-uniform per row).
// ---------------------------------------------------------------------------
__global__ __launch_bounds__(32)
void triangulate_kernel(const float* __restrict__ proj,
                        const float* __restrict__ confid,
                        float* __restrict__ out)
{
    const int lane  = threadIdx.x;          // 0..31
    const int quad  = lane >> 2;            // 0..7 : joint within warp
    const int ql    = lane & 3;             // 0..3 : row-group within joint
    const int qbase = lane & ~3;            // first lane of this quad
    const int joint = blockIdx.x * 8 + quad; // 0..1279 (grid=160 exact)
    const int b = joint / NJ;
    const int j = joint % NJ;

    // ---- confidence normalization (replicated; broadcast loads) -----------
    float csum = 0.f;
#pragma unroll
    for (int c = 0; c < NUM_CAMS; c++)
        csum += confid[(b * NUM_CAMS + c) * NJ + j];
    const float rs = 1.0f / csum;

    // ---- this lane's 3 rows of A (rows 3*ql .. 3*ql+2) ---------------------
    const float* kpc = out + OFF_KPC;
    float Af[3][4];
#pragma unroll
    for (int i = 0; i < 3; i++) {
        int n   = 3 * ql + i;
        int cam = n >> 1;
        int par = n & 1;
        const float* Pc = proj + (b * NUM_CAMS + cam) * 12;
        float4 prow = *reinterpret_cast<const float4*>(Pc + par * 4);   // row 0 or 1
        float4 p2   = *reinterpret_cast<const float4*>(Pc + 8);         // row 2
        float  cf   = fmaf(confid[(b * NUM_CAMS + cam) * NJ + j], rs, 1e-5f);
        float  uv   = kpc[((b * NUM_CAMS + cam) * NJ + j) * 3 + par];   // px or py
        Af[i][0] = (p2.x * uv - prow.x) * cf;
        Af[i][1] = (p2.y * uv - prow.y) * cf;
        Af[i][2] = (p2.z * uv - prow.z) * cf;
        Af[i][3] = (p2.w * uv - prow.w) * cf;
    }

    // ---- fp64 M = AtA: per-lane partials over 3 rows, quad butterfly sum ---
    const int PK[10] = {0,0,0,0,1,1,1,2,2,3};
    const int PL[10] = {0,1,2,3,1,2,3,2,3,3};
    double Ad[3][4];
#pragma unroll
    for (int i = 0; i < 3; i++)
#pragma unroll
        for (int k = 0; k < 4; k++) Ad[i][k] = (double)Af[i][k];

    double M[4][4];
#pragma unroll
    for (int e = 0; e < 10; e++) {
        double v = Ad[0][PK[e]] * Ad[0][PL[e]];
        v = fma(Ad[1][PK[e]], Ad[1][PL[e]], v);
        v = fma(Ad[2][PK[e]], Ad[2][PL[e]], v);
        v += __shfl_xor_sync(0xffffffffu, v, 1);
        v += __shfl_xor_sync(0xffffffffu, v, 2);
        M[PK[e]][PL[e]] = v;
        M[PL[e]][PK[e]] = v;
    }

    // ---- fp32 Jacobi: M replicated, V row-distributed (lane ql owns row ql)
    float M32[4][4];
#pragma unroll
    for (int k = 0; k < 4; k++)
#pragma unroll
        for (int l = 0; l < 4; l++) M32[k][l] = (float)M[k][l];

    float Vrow[4] = { (ql == 0) ? 1.0f : 0.0f, (ql == 1) ? 1.0f : 0.0f,
                      (ql == 2) ? 1.0f : 0.0f, (ql == 3) ? 1.0f : 0.0f };

#pragma unroll
    for (int sweep = 0; sweep < 5; sweep++) {
        jrot_pair<0,1,2,3>(M32, Vrow);
        jrot_pair<0,2,1,3>(M32, Vrow);
        jrot_pair<0,3,1,2>(M32, Vrow);
    }

    // seed selection: fp32 diagonal argmin (replicated), gather row components
    int mi = 0; float dmf = M32[0][0];
    if (M32[1][1] < dmf) { dmf = M32[1][1]; mi = 1; }
    if (M32[2][2] < dmf) { dmf = M32[2][2]; mi = 2; }
    if (M32[3][3] < dmf) { dmf = M32[3][3]; mi = 3; }

    float xf = (mi == 0) ? Vrow[0] : (mi == 1) ? Vrow[1]
             : (mi == 2) ? Vrow[2] : Vrow[3];      // this lane's component
    double x0 = (double)__shfl_sync(0xffffffffu, xf, qbase + 0);
    double x1 = (double)__shfl_sync(0xffffffffu, xf, qbase + 1);
    double x2 = (double)__shfl_sync(0xffffffffu, xf, qbase + 2);
    double x3 = (double)__shfl_sync(0xffffffffu, xf, qbase + 3);

    // ---- adjugate of symmetric M: sub-dets + J entries replicated ----------
    double s0 = fma(M[0][0], M[1][1], -M[1][0] * M[0][1]);
    double s1 = fma(M[0][0], M[1][2], -M[1][0] * M[0][2]);
    double s2 = fma(M[0][0], M[1][3], -M[1][0] * M[0][3]);
    double s3 = fma(M[0][1], M[1][2], -M[1][1] * M[0][2]);
    double s4 = fma(M[0][1], M[1][3], -M[1][1] * M[0][3]);
    double s5 = fma(M[0][2], M[1][3], -M[1][2] * M[0][3]);
    double c5 = fma(M[2][2], M[3][3], -M[3][2] * M[2][3]);
    double c4 = fma(M[2][1], M[3][3], -M[3][1] * M[2][3]);
    double c3 = fma(M[2][1], M[3][2], -M[3][1] * M[2][2]);
    double c2 = fma(M[2][0], M[3][3], -M[3][0] * M[2][3]);
    double c1 = fma(M[2][0], M[3][2], -M[3][0] * M[2][2]);

    double J00 = fma( M[1][1], c5, fma(-M[1][2], c4,  M[1][3] * c3));
    double J01 = fma(-M[0][1], c5, fma( M[0][2], c4, -M[0][3] * c3));
    double J02 = fma( M[3][1], s5, fma(-M[3][2], s4,  M[3][3] * s3));
    double J03 = fma(-M[2][1], s5, fma( M[2][2], s4, -M[2][3] * s3));
    double J11 = fma( M[0][0], c5, fma(-M[0][2], c2,  M[0][3] * c1));
    double J12 = fma(-M[3][0], s5, fma( M[3][2], s2, -M[3][3] * s1));
    double J13 = fma( M[2][0], s5, fma(-M[2][2], s2,  M[2][3] * s1));
    double J22 = fma( M[3][0], s4, fma(-M[3][1], s2,  M[3][3] * s0));
    double J23 = fma(-M[2][0], s4, fma( M[2][1], s2, -M[2][3] * s0));
    double J33 = fma( M[2][0], s3, fma(-M[2][1], s1,  M[2][2] * s0));

    // this lane's J row (cheap ALU selects; J symmetric)
    double Jr0 = (ql == 0) ? J00 : (ql == 1) ? J01 : (ql == 2) ? J02 : J03;
    double Jr1 = (ql == 0) ? J01 : (ql == 1) ? J11 : (ql == 2) ? J12 : J13;
    double Jr2 = (ql == 0) ? J02 : (ql == 1) ? J12 : (ql == 2) ? J22 : J23;
    double Jr3 = (ql == 0) ? J03 : (ql == 1) ? J13 : (ql == 2) ? J23 : J33;

    // two adjugate applications, ROW-DISTRIBUTED (1 component per lane);
    // quad gathers via shuffles. Same arithmetic per row as the replicated
    // form; no mid renorm needed (||x||^2 << fp64 max).
    double yl = fma(Jr0, x0, fma(Jr1, x1, fma(Jr2, x2, Jr3 * x3)));
    double y0 = __shfl_sync(0xffffffffu, yl, qbase + 0);
    double y1 = __shfl_sync(0xffffffffu, yl, qbase + 1);
    double y2 = __shfl_sync(0xffffffffu, yl, qbase + 2);
    double y3 = __shfl_sync(0xffffffffu, yl, qbase + 3);
    double xl = fma(Jr0, y0, fma(Jr1, y1, fma(Jr2, y2, Jr3 * y3)));
    x0 = __shfl_sync(0xffffffffu, xl, qbase + 0);
    x1 = __shfl_sync(0xffffffffu, xl, qbase + 1);
    x2 = __shfl_sync(0xffffffffu, xl, qbase + 2);
    x3 = __shfl_sync(0xffffffffu, xl, qbase + 3);

    // exact pow2 renorm; nrm2 of scaled vector is (n2*sc)*sc EXACTLY
    double n2 = fma(x0, x0, fma(x1, x1, fma(x2, x2, x3 * x3)));
    double sc = pow2_inv_sqrt_approx(n2);
    x0 *= sc; x1 *= sc; x2 *= sc; x3 *= sc;
    double nrm2 = (n2 * sc) * sc;               // in ~[0.25, 4]

    // kp_3d = x[:3]/x[3]  (normalization- and sign-invariant); lane 0 of quad
    if (ql == 0) {
        double inv = fast_drcp(x3);
        float* kp3 = out + OFF_KP3D + joint * 3;
        kp3[0] = (float)(x0 * inv);
        kp3[1] = (float)(x1 * inv);
        kp3[2] = (float)(x2 * inv);
    }

    // res = (sum_n |A[n,:].x|) / ||x|| -- rows distributed, quad-reduced
    double acc = 0.0;
#pragma unroll
    for (int i = 0; i < 3; i++) {
        double dsum = fma(Ad[i][0], x0, fma(Ad[i][1], x1,
                      fma(Ad[i][2], x2, Ad[i][3] * x3)));
        acc += fabs(dsum);
    }
    acc += __shfl_xor_sync(0xffffffffu, acc, 1);
    acc += __shfl_xor_sync(0xffffffffu, acc, 2);
    if (ql == 0)
        out[OFF_RES + joint] = (float)(acc * fast_drsqrt(nrm2));
}

// ---------------------------------------------------------------------------
extern "C" void kernel_launch(void* const* d_in, const int* in_sizes, int n_in,
                              void* d_out, int out_size)
{
    const float* heatmap = (const float*)d_in[0];  // (384, 20, 64, 64)
    const float* proj    = (const float*)d_in[1];  // (64, 6, 3, 4)
    const float* confid  = (const float*)d_in[2];  // (384, 20)
    float* out = (float*)d_out;                    // 51200 floats

    softargmax_kernel<<<NMAPS, 256>>>(heatmap, out);
    triangulate_kernel<<<160, 32>>>(proj, confid, out);   // 160*8 = 1280 joints
}